// round 15
// baseline (speedup 1.0000x reference)
#include <cuda_runtime.h>
#include <cuda_bf16.h>
#include <cstdint>

// Problem constants
#define T_SEQ 65536
#define F_IN  512
#define H_DIM 64
#define G_DIM 256    // 4*H
#define NT4   (T_SEQ / 4)

typedef unsigned long long ull;

// Scratch (allocation-free rule: __device__ globals)
__device__ __align__(16) float4 g_xgA[(size_t)(NT4 + 2) * 128];
__device__ __align__(16) float4 g_xgB[(size_t)(NT4 + 2) * 128];
__device__ float g_hfin[H_DIM];

// ---------------- packed f32x2 helpers ----------------
static __device__ __forceinline__ ull fma2(ull a, ull b, ull c) {
    ull d;
    asm("fma.rn.f32x2 %0, %1, %2, %3;" : "=l"(d) : "l"(a), "l"(b), "l"(c));
    return d;
}
static __device__ __forceinline__ ull add2(ull a, ull b) {
    ull d;
    asm("add.rn.f32x2 %0, %1, %2;" : "=l"(d) : "l"(a), "l"(b));
    return d;
}
static __device__ __forceinline__ float2 upk(ull a) {
    float2 r;
    asm("mov.b64 {%0, %1}, %2;" : "=f"(r.x), "=f"(r.y) : "l"(a));
    return r;
}
static __device__ __forceinline__ ull pk2(float x, float y) {
    ull r;
    asm("mov.b64 %0, {%1, %2};" : "=l"(r) : "f"(x), "f"(y));
    return r;
}

// ---------------- single-instruction MUFU.TANH ----------------
static __device__ __forceinline__ float tanhap(float x) {
    float r;
    asm("tanh.approx.f32 %0, %1;" : "=f"(r) : "f"(x));
    return r;
}

// Recurrence thread mapping for gate-row r (= g*64 + u):
// warp w = u>>4 owns units [16w,16w+16); even lane: gates (i,g); odd: (f,o)
static __device__ __forceinline__ int map_tid(int g, int u) {
    int odd = g & 1;                 // i,g -> even ; f,o -> odd
    return ((u >> 4) << 5) + ((u & 15) << 1) + odd;
}

// =====================================================================
// Kernel 1: xg = x @ W_ih.T + (b_ih + b_hh), permuted into slot streams.
// BM=128, BN=128, double-buffered smem. W tile is stored DUPLICATED
// (wsD[kk][2c] = wsD[kk][2c+1] = w[c]) so the f32x2 b-operands are read
// directly: per kk = 2 a-LDS.128 + 4 b-LDS.128 + 32 fma2, zero dup-MOVs.
// fma2 sequence / k-order identical -> xg bit-identical to prior rounds.
// Grid: blockIdx.x = colgroup (2), blockIdx.y = t-tile (512) for L2 x-reuse.
// =====================================================================
#define BM 128
#define BN 128
#define XSTRIDE 132   // 128 + 4 pad floats (16B-aligned rows)
#define WSTRIDE 260   // 2*128 + 4 pad floats (duplicated row)
#define NKT (F_IN / 16)
__global__ void __launch_bounds__(256)
gemm_xg(const float* __restrict__ x,
        const float* __restrict__ Wih,
        const float* __restrict__ bih,
        const float* __restrict__ bhh) {
    __shared__ __align__(16) float xsT[2][16][XSTRIDE];   // [buf][kk][row]
    __shared__ __align__(16) float wsD[2][16][WSTRIDE];   // [buf][kk][2*col dup]
    const int tid = threadIdx.x;           // 0..255
    const int tx = tid & 15;               // col group
    const int ty = tid >> 4;               // row group: rows ty*8..ty*8+7
    const int row0 = blockIdx.y * BM;      // t-tile base
    const int col0 = blockIdx.x * BN;      // gate-row tile base

    // acc2[rp][jj]: rp = row pair (rows 2rp,2rp+1), jj = col slot
    // col(jj) = (jj<4) ? tx*4+jj : 64 + tx*4 + (jj-4)
    ull acc2[4][8];
#pragma unroll
    for (int i = 0; i < 4; i++)
#pragma unroll
        for (int j = 0; j < 8; j++) acc2[i][j] = 0ull;

    // Loader: both tiles are 128x16 = 512 float4 slots, 2 per thread.
    const int r0 = tid >> 2, r1 = (tid + 256) >> 2;
    const int kq = (tid & 3) * 4;

#define STS_TILE(BUF, XV0, XV1, WV0, WV1) do {                                \
        xsT[BUF][kq + 0][r0] = (XV0).x; xsT[BUF][kq + 1][r0] = (XV0).y;       \
        xsT[BUF][kq + 2][r0] = (XV0).z; xsT[BUF][kq + 3][r0] = (XV0).w;       \
        xsT[BUF][kq + 0][r1] = (XV1).x; xsT[BUF][kq + 1][r1] = (XV1).y;       \
        xsT[BUF][kq + 2][r1] = (XV1).z; xsT[BUF][kq + 3][r1] = (XV1).w;       \
        *(ull*)&wsD[BUF][kq + 0][2 * r0] = pk2((WV0).x, (WV0).x);             \
        *(ull*)&wsD[BUF][kq + 1][2 * r0] = pk2((WV0).y, (WV0).y);             \
        *(ull*)&wsD[BUF][kq + 2][2 * r0] = pk2((WV0).z, (WV0).z);             \
        *(ull*)&wsD[BUF][kq + 3][2 * r0] = pk2((WV0).w, (WV0).w);             \
        *(ull*)&wsD[BUF][kq + 0][2 * r1] = pk2((WV1).x, (WV1).x);             \
        *(ull*)&wsD[BUF][kq + 1][2 * r1] = pk2((WV1).y, (WV1).y);             \
        *(ull*)&wsD[BUF][kq + 2][2 * r1] = pk2((WV1).z, (WV1).z);             \
        *(ull*)&wsD[BUF][kq + 3][2 * r1] = pk2((WV1).w, (WV1).w);             \
    } while (0)

    // Prologue: load ktile 0 into buffer 0.
    {
        float4 xv0 = *(const float4*)(x + (size_t)(row0 + r0) * F_IN + kq);
        float4 xv1 = *(const float4*)(x + (size_t)(row0 + r1) * F_IN + kq);
        float4 wv0 = *(const float4*)(Wih + (size_t)(col0 + r0) * F_IN + kq);
        float4 wv1 = *(const float4*)(Wih + (size_t)(col0 + r1) * F_IN + kq);
        STS_TILE(0, xv0, xv1, wv0, wv1);
    }
    __syncthreads();

    for (int kt = 0; kt < NKT; kt++) {
        const int cur = kt & 1;
        float4 nx0, nx1, nw0, nw1;
        if (kt + 1 < NKT) {
            const int kb = (kt + 1) * 16 + kq;
            nx0 = *(const float4*)(x + (size_t)(row0 + r0) * F_IN + kb);
            nx1 = *(const float4*)(x + (size_t)(row0 + r1) * F_IN + kb);
            nw0 = *(const float4*)(Wih + (size_t)(col0 + r0) * F_IN + kb);
            nw1 = *(const float4*)(Wih + (size_t)(col0 + r1) * F_IN + kb);
        }
#pragma unroll
        for (int kk = 0; kk < 16; kk++) {
            ulonglong2 a01 = *(const ulonglong2*)&xsT[cur][kk][ty * 8];
            ulonglong2 a23 = *(const ulonglong2*)&xsT[cur][kk][ty * 8 + 4];
            // duplicated b pairs, read directly as f32x2 operands
            ulonglong2 bp01 = *(const ulonglong2*)&wsD[cur][kk][tx * 8];
            ulonglong2 bp23 = *(const ulonglong2*)&wsD[cur][kk][tx * 8 + 4];
            ulonglong2 bp45 = *(const ulonglong2*)&wsD[cur][kk][128 + tx * 8];
            ulonglong2 bp67 = *(const ulonglong2*)&wsD[cur][kk][128 + tx * 8 + 4];
            acc2[0][0] = fma2(a01.x, bp01.x, acc2[0][0]);
            acc2[0][1] = fma2(a01.x, bp01.y, acc2[0][1]);
            acc2[0][2] = fma2(a01.x, bp23.x, acc2[0][2]);
            acc2[0][3] = fma2(a01.x, bp23.y, acc2[0][3]);
            acc2[0][4] = fma2(a01.x, bp45.x, acc2[0][4]);
            acc2[0][5] = fma2(a01.x, bp45.y, acc2[0][5]);
            acc2[0][6] = fma2(a01.x, bp67.x, acc2[0][6]);
            acc2[0][7] = fma2(a01.x, bp67.y, acc2[0][7]);
            acc2[1][0] = fma2(a01.y, bp01.x, acc2[1][0]);
            acc2[1][1] = fma2(a01.y, bp01.y, acc2[1][1]);
            acc2[1][2] = fma2(a01.y, bp23.x, acc2[1][2]);
            acc2[1][3] = fma2(a01.y, bp23.y, acc2[1][3]);
            acc2[1][4] = fma2(a01.y, bp45.x, acc2[1][4]);
            acc2[1][5] = fma2(a01.y, bp45.y, acc2[1][5]);
            acc2[1][6] = fma2(a01.y, bp67.x, acc2[1][6]);
            acc2[1][7] = fma2(a01.y, bp67.y, acc2[1][7]);
            acc2[2][0] = fma2(a23.x, bp01.x, acc2[2][0]);
            acc2[2][1] = fma2(a23.x, bp01.y, acc2[2][1]);
            acc2[2][2] = fma2(a23.x, bp23.x, acc2[2][2]);
            acc2[2][3] = fma2(a23.x, bp23.y, acc2[2][3]);
            acc2[2][4] = fma2(a23.x, bp45.x, acc2[2][4]);
            acc2[2][5] = fma2(a23.x, bp45.y, acc2[2][5]);
            acc2[2][6] = fma2(a23.x, bp67.x, acc2[2][6]);
            acc2[2][7] = fma2(a23.x, bp67.y, acc2[2][7]);
            acc2[3][0] = fma2(a23.y, bp01.x, acc2[3][0]);
            acc2[3][1] = fma2(a23.y, bp01.y, acc2[3][1]);
            acc2[3][2] = fma2(a23.y, bp23.x, acc2[3][2]);
            acc2[3][3] = fma2(a23.y, bp23.y, acc2[3][3]);
            acc2[3][4] = fma2(a23.y, bp45.x, acc2[3][4]);
            acc2[3][5] = fma2(a23.y, bp45.y, acc2[3][5]);
            acc2[3][6] = fma2(a23.y, bp67.x, acc2[3][6]);
            acc2[3][7] = fma2(a23.y, bp67.y, acc2[3][7]);
        }
        if (kt + 1 < NKT) STS_TILE(cur ^ 1, nx0, nx1, nw0, nw1);
        __syncthreads();
    }
#undef STS_TILE

    // Epilogue: thread's 8 rows = 2 float4 t-blocks; 8 cols (two groups).
    const int tb4 = (row0 + ty * 8) >> 2;
#pragma unroll
    for (int jj = 0; jj < 8; jj++) {
        const int col = col0 + ((jj < 4) ? (tx * 4 + jj) : (64 + tx * 4 + jj - 4));
        const float bj = bih[col] + bhh[col];
        const int gg = col >> 6;            // gate 0=i 1=f 2=g 3=o
        const int uu = col & 63;
        const int p = map_tid(gg, uu);
        const float sc = (gg == 2) ? 1.0f : 0.5f;   // sigmoid pre-scale (exact)
        float v[8];
#pragma unroll
        for (int rp = 0; rp < 4; rp++) {
            float2 pv = upk(acc2[rp][jj]);
            v[2 * rp] = pv.x;
            v[2 * rp + 1] = pv.y;
        }
        float4* buf = (gg >= 2) ? g_xgB : g_xgA;    // slot B = gates g,o
#pragma unroll
        for (int m = 0; m < 2; m++) {
            float4 o;
            o.x = sc * (v[4 * m + 0] + bj);
            o.y = sc * (v[4 * m + 1] + bj);
            o.z = sc * (v[4 * m + 2] + bj);
            o.w = sc * (v[4 * m + 3] + bj);
            buf[(size_t)(tb4 + m) * 128 + p] = o;
        }
    }
}

// =====================================================================
// Kernel 2: persistent single-block LSTM recurrence, 128 threads
// (4 warps, 1 per SMSP). Even lane: gates (i, g) of unit u; odd: (f, o).
// One __syncthreads per step; gate product crosses via one shfl.
// (Measured best structure, ~347 cyc/step — verbatim.)
// =====================================================================
__global__ void __launch_bounds__(128, 1)
lstm_rec(const float* __restrict__ Whh,
         const float* __restrict__ h0,
         const float* __restrict__ c0) {
    __shared__ __align__(16) float h_sh[2][H_DIM];
    const int tid = threadIdx.x;          // 0..127
    const int l = tid & 31;
    const int u = ((tid >> 5) << 4) + (l >> 1);   // hidden unit
    const int odd = l & 1;
    const int rA = (odd ? 64 : 0) + u;    // i or f   (sigmoid: pre-scale 0.5)
    const int rB = (odd ? 192 : 128) + u; // g or o   (tanh 1.0 / sigmoid 0.5)
    const float scA = 0.5f;
    const float scB = odd ? 0.5f : 1.0f;

    // W_hh rows -> packed f32x2 registers, pre-scaled (x0.5 exact)
    ull wA[32], wB[32];
    {
        const float2* pa = (const float2*)(Whh + (size_t)rA * H_DIM);
        const float2* pb = (const float2*)(Whh + (size_t)rB * H_DIM);
#pragma unroll
        for (int i = 0; i < 32; i++) {
            float2 va = pa[i], vb = pb[i];
            wA[i] = pk2(scA * va.x, scA * va.y);
            wB[i] = pk2(scB * vb.x, scB * vb.y);
        }
    }

    const float aB = odd ? 0.5f : 1.0f;
    const float oB = odd ? 0.5f : 0.0f;

    float c = odd ? c0[u] : 0.0f;
    float h = 0.0f;
    if (tid < H_DIM) h_sh[0][tid] = h0[tid];

#define STEP(XA, XB, RB, WB) do {                                             \
        __syncthreads();                                                      \
        const ulonglong2* hp = (const ulonglong2*)h_sh[RB];                   \
        ull a0 = 0, a1 = 0, a2 = 0, a3 = 0;                                   \
        ull b0 = 0, b1 = 0, b2 = 0, b3 = 0;                                   \
        _Pragma("unroll")                                                     \
        for (int i = 0; i < 8; i++) {                                         \
            ulonglong2 hv = hp[2 * i], hw = hp[2 * i + 1];                    \
            a0 = fma2(hv.x, wA[4 * i + 0], a0);                               \
            b0 = fma2(hv.x, wB[4 * i + 0], b0);                               \
            a1 = fma2(hv.y, wA[4 * i + 1], a1);                               \
            b1 = fma2(hv.y, wB[4 * i + 1], b1);                               \
            a2 = fma2(hw.x, wA[4 * i + 2], a2);                               \
            b2 = fma2(hw.x, wB[4 * i + 2], b2);                               \
            a3 = fma2(hw.y, wA[4 * i + 3], a3);                               \
            b3 = fma2(hw.y, wB[4 * i + 3], b3);                               \
        }                                                                     \
        float2 sA = upk(add2(add2(a0, a1), add2(a2, a3)));                    \
        float2 sB = upk(add2(add2(b0, b1), add2(b2, b3)));                    \
        float preA = (XA) + sA.x + sA.y;                                      \
        float preB = (XB) + sB.x + sB.y;                                      \
        float vA = fmaf(0.5f, tanhap(preA), 0.5f);   /* sigmoid (pre-scaled)*/\
        float vB = fmaf(aB, tanhap(preB), oB);       /* tanh / sigmoid */     \
        float pr = __shfl_sync(0xffffffffu, vA * vB, l & 30);  /* i*g~ */     \
        if (odd) {                                                            \
            c = fmaf(vA, c, pr);            /* c = f*c + i*g~ */              \
            h = vB * tanhap(c);             /* h = o*tanh(c) */               \
            h_sh[WB][u] = h;                                                  \
        }                                                                     \
    } while (0)

    // Streamed xg: one LDG.128 pair per 4 steps, prefetched 2 blocks ahead
    // (padded arrays -> no bounds predicate).
    float4 xA0 = g_xgA[tid],       xB0 = g_xgB[tid];
    float4 xA1 = g_xgA[128 + tid], xB1 = g_xgB[128 + tid];
    for (int tb = 0; tb < NT4; tb++) {
        float4 xA2 = g_xgA[(size_t)(tb + 2) * 128 + tid];
        float4 xB2 = g_xgB[(size_t)(tb + 2) * 128 + tid];
        STEP(xA0.x, xB0.x, 0, 1);
        STEP(xA0.y, xB0.y, 1, 0);
        STEP(xA0.z, xB0.z, 0, 1);
        STEP(xA0.w, xB0.w, 1, 0);
        xA0 = xA1; xA1 = xA2;
        xB0 = xB1; xB1 = xB2;
    }
#undef STEP

    if (odd) g_hfin[u] = h;
}

// =====================================================================
// Kernel 3: out[f] = sigmoid(h_last . W_fc[f] + b_fc[f]),  f < 512
// =====================================================================
__global__ void fc_out(const float* __restrict__ Wfc,
                       const float* __restrict__ bfc,
                       float* __restrict__ out) {
    __shared__ float hsm[H_DIM];
    const int tid = threadIdx.x;   // 0..511
    if (tid < H_DIM) hsm[tid] = g_hfin[tid];
    __syncthreads();
    float acc = bfc[tid];
    const float* wr = Wfc + (size_t)tid * H_DIM;
#pragma unroll
    for (int k = 0; k < H_DIM; k++) acc = fmaf(wr[k], hsm[k], acc);
    out[tid] = 1.0f / (1.0f + __expf(-acc));
}

extern "C" void kernel_launch(void* const* d_in, const int* in_sizes, int n_in,
                              void* d_out, int out_size) {
    const float* x   = (const float*)d_in[0];
    const float* h0  = (const float*)d_in[1];
    const float* c0  = (const float*)d_in[2];
    const float* Wih = (const float*)d_in[3];
    const float* Whh = (const float*)d_in[4];
    const float* bih = (const float*)d_in[5];
    const float* bhh = (const float*)d_in[6];
    const float* Wfc = (const float*)d_in[7];
    const float* bfc = (const float*)d_in[8];
    float* out = (float*)d_out;

    dim3 ggrid(G_DIM / BN, T_SEQ / BM);   // x = colgroup (2), y = t-tile (512)
    gemm_xg<<<ggrid, 256>>>(x, Wih, bih, bhh);
    lstm_rec<<<1, 128>>>(Whh, h0, c0);
    fc_out<<<1, 512>>>(Wfc, bfc, out);
}

// round 16
// speedup vs baseline: 1.0188x; 1.0188x over previous
#include <cuda_runtime.h>
#include <cuda_bf16.h>
#include <cstdint>

// Problem constants
#define T_SEQ 65536
#define F_IN  512
#define H_DIM 64
#define G_DIM 256    // 4*H
#define NT4   (T_SEQ / 4)

typedef unsigned long long ull;

// Scratch (allocation-free rule: __device__ globals)
__device__ __align__(16) float4 g_xgA[(size_t)(NT4 + 2) * 128];
__device__ __align__(16) float4 g_xgB[(size_t)(NT4 + 2) * 128];
__device__ float g_hfin[H_DIM];

// ---------------- packed f32x2 helpers ----------------
static __device__ __forceinline__ ull fma2(ull a, ull b, ull c) {
    ull d;
    asm("fma.rn.f32x2 %0, %1, %2, %3;" : "=l"(d) : "l"(a), "l"(b), "l"(c));
    return d;
}
static __device__ __forceinline__ ull add2(ull a, ull b) {
    ull d;
    asm("add.rn.f32x2 %0, %1, %2;" : "=l"(d) : "l"(a), "l"(b));
    return d;
}
static __device__ __forceinline__ float2 upk(ull a) {
    float2 r;
    asm("mov.b64 {%0, %1}, %2;" : "=f"(r.x), "=f"(r.y) : "l"(a));
    return r;
}
static __device__ __forceinline__ ull pk2(float x, float y) {
    ull r;
    asm("mov.b64 %0, {%1, %2};" : "=l"(r) : "f"(x), "f"(y));
    return r;
}

// ---------------- single-instruction MUFU.TANH ----------------
static __device__ __forceinline__ float tanhap(float x) {
    float r;
    asm("tanh.approx.f32 %0, %1;" : "=f"(r) : "f"(x));
    return r;
}

// Recurrence thread mapping for gate-row r (= g*64 + u):
// warp w = u>>4 owns units [16w,16w+16); even lane: gates (i,g); odd: (f,o)
static __device__ __forceinline__ int map_tid(int g, int u) {
    int odd = g & 1;                 // i,g -> even ; f,o -> odd
    return ((u >> 4) << 5) + ((u & 15) << 1) + odd;
}

// =====================================================================
// Kernel 1: xg = x @ W_ih.T + (b_ih + b_hh), permuted into slot streams.
// BM=128, BN=128, double-buffered smem, 512 THREADS (4 rows x 8 cols per
// thread) with __launch_bounds__(512,2) -> 2 CTAs/SM = 32 warps (2x R14's
// latency-hiding). Per kk per thread: 1 a-LDS.128 + 2 b-LDS.128 + 8 dup-MOV
// + 16 fma2. k-order per (row,col) identical -> xg bit-identical.
// Grid: blockIdx.x = colgroup (2), blockIdx.y = t-tile (512) for L2 x-reuse.
// =====================================================================
#define BM 128
#define BN 128
#define XSTRIDE 132   // 128 + 4 pad floats (16B-aligned rows)
#define NKT (F_IN / 16)
__global__ void __launch_bounds__(512, 2)
gemm_xg(const float* __restrict__ x,
        const float* __restrict__ Wih,
        const float* __restrict__ bih,
        const float* __restrict__ bhh) {
    __shared__ __align__(16) float xsT[2][16][XSTRIDE];   // [buf][kk][row]
    __shared__ __align__(16) float wsT[2][16][XSTRIDE];   // [buf][kk][col]
    const int tid = threadIdx.x;           // 0..511
    const int tx = tid & 15;               // col group (8 cols: tx*4 & 64+tx*4)
    const int ty = tid >> 4;               // row group: rows ty*4..ty*4+3
    const int row0 = blockIdx.y * BM;      // t-tile base
    const int col0 = blockIdx.x * BN;      // gate-row tile base

    // acc2[rp][jj]: rp = row pair within the thread's 4 rows, jj = col slot
    // col(jj) = (jj<4) ? tx*4+jj : 64 + tx*4 + (jj-4)
    ull acc2[2][8];
#pragma unroll
    for (int i = 0; i < 2; i++)
#pragma unroll
        for (int j = 0; j < 8; j++) acc2[i][j] = 0ull;

    // Loader: both tiles are 128x16 = 512 float4 slots, ONE per thread.
    const int r0 = tid >> 2;
    const int kq = (tid & 3) * 4;

#define STS_TILE(BUF, XV, WV) do {                                            \
        xsT[BUF][kq + 0][r0] = (XV).x; xsT[BUF][kq + 1][r0] = (XV).y;         \
        xsT[BUF][kq + 2][r0] = (XV).z; xsT[BUF][kq + 3][r0] = (XV).w;         \
        wsT[BUF][kq + 0][r0] = (WV).x; wsT[BUF][kq + 1][r0] = (WV).y;         \
        wsT[BUF][kq + 2][r0] = (WV).z; wsT[BUF][kq + 3][r0] = (WV).w;         \
    } while (0)

    // Prologue: load ktile 0 into buffer 0.
    {
        float4 xv = *(const float4*)(x + (size_t)(row0 + r0) * F_IN + kq);
        float4 wv = *(const float4*)(Wih + (size_t)(col0 + r0) * F_IN + kq);
        STS_TILE(0, xv, wv);
    }
    __syncthreads();

    for (int kt = 0; kt < NKT; kt++) {
        const int cur = kt & 1;
        float4 nx, nw;
        if (kt + 1 < NKT) {
            const int kb = (kt + 1) * 16 + kq;
            nx = *(const float4*)(x + (size_t)(row0 + r0) * F_IN + kb);
            nw = *(const float4*)(Wih + (size_t)(col0 + r0) * F_IN + kb);
        }
#pragma unroll
        for (int kk = 0; kk < 16; kk++) {
            // rows ty*4..ty*4+3 as 2 packed pairs (1 LDS.128, 2 addrs/warp)
            ulonglong2 a01 = *(const ulonglong2*)&xsT[cur][kk][ty * 4];
            // cols: two float4 groups at 2-phase conflict
            float4 bv0 = *(const float4*)&wsT[cur][kk][tx * 4];
            float4 bv1 = *(const float4*)&wsT[cur][kk][64 + tx * 4];
            ull b0 = pk2(bv0.x, bv0.x), b1 = pk2(bv0.y, bv0.y);
            ull b2 = pk2(bv0.z, bv0.z), b3 = pk2(bv0.w, bv0.w);
            ull b4 = pk2(bv1.x, bv1.x), b5 = pk2(bv1.y, bv1.y);
            ull b6 = pk2(bv1.z, bv1.z), b7 = pk2(bv1.w, bv1.w);
            acc2[0][0] = fma2(a01.x, b0, acc2[0][0]);
            acc2[0][1] = fma2(a01.x, b1, acc2[0][1]);
            acc2[0][2] = fma2(a01.x, b2, acc2[0][2]);
            acc2[0][3] = fma2(a01.x, b3, acc2[0][3]);
            acc2[0][4] = fma2(a01.x, b4, acc2[0][4]);
            acc2[0][5] = fma2(a01.x, b5, acc2[0][5]);
            acc2[0][6] = fma2(a01.x, b6, acc2[0][6]);
            acc2[0][7] = fma2(a01.x, b7, acc2[0][7]);
            acc2[1][0] = fma2(a01.y, b0, acc2[1][0]);
            acc2[1][1] = fma2(a01.y, b1, acc2[1][1]);
            acc2[1][2] = fma2(a01.y, b2, acc2[1][2]);
            acc2[1][3] = fma2(a01.y, b3, acc2[1][3]);
            acc2[1][4] = fma2(a01.y, b4, acc2[1][4]);
            acc2[1][5] = fma2(a01.y, b5, acc2[1][5]);
            acc2[1][6] = fma2(a01.y, b6, acc2[1][6]);
            acc2[1][7] = fma2(a01.y, b7, acc2[1][7]);
        }
        if (kt + 1 < NKT) STS_TILE(cur ^ 1, nx, nw);
        __syncthreads();
    }
#undef STS_TILE

    // Epilogue: thread's 4 rows = exactly one float4 t-block; 8 cols.
    const int tb4 = (row0 + ty * 4) >> 2;
#pragma unroll
    for (int jj = 0; jj < 8; jj++) {
        const int col = col0 + ((jj < 4) ? (tx * 4 + jj) : (64 + tx * 4 + jj - 4));
        const float bj = bih[col] + bhh[col];
        const int gg = col >> 6;            // gate 0=i 1=f 2=g 3=o
        const int uu = col & 63;
        const int p = map_tid(gg, uu);
        const float sc = (gg == 2) ? 1.0f : 0.5f;   // sigmoid pre-scale (exact)
        float2 p0 = upk(acc2[0][jj]);
        float2 p1 = upk(acc2[1][jj]);
        float4 o;
        o.x = sc * (p0.x + bj);
        o.y = sc * (p0.y + bj);
        o.z = sc * (p1.x + bj);
        o.w = sc * (p1.y + bj);
        float4* buf = (gg >= 2) ? g_xgB : g_xgA;    // slot B = gates g,o
        buf[(size_t)tb4 * 128 + p] = o;
    }
}

// =====================================================================
// Kernel 2: persistent single-block LSTM recurrence, 128 threads
// (4 warps, 1 per SMSP). Even lane: gates (i, g) of unit u; odd: (f, o).
// One __syncthreads per step; gate product crosses via one shfl.
// (Measured best structure, ~347 cyc/step — verbatim R14.)
// =====================================================================
__global__ void __launch_bounds__(128, 1)
lstm_rec(const float* __restrict__ Whh,
         const float* __restrict__ h0,
         const float* __restrict__ c0) {
    __shared__ __align__(16) float h_sh[2][H_DIM];
    const int tid = threadIdx.x;          // 0..127
    const int l = tid & 31;
    const int u = ((tid >> 5) << 4) + (l >> 1);   // hidden unit
    const int odd = l & 1;
    const int rA = (odd ? 64 : 0) + u;    // i or f   (sigmoid: pre-scale 0.5)
    const int rB = (odd ? 192 : 128) + u; // g or o   (tanh 1.0 / sigmoid 0.5)
    const float scA = 0.5f;
    const float scB = odd ? 0.5f : 1.0f;

    // W_hh rows -> packed f32x2 registers, pre-scaled (x0.5 exact)
    ull wA[32], wB[32];
    {
        const float2* pa = (const float2*)(Whh + (size_t)rA * H_DIM);
        const float2* pb = (const float2*)(Whh + (size_t)rB * H_DIM);
#pragma unroll
        for (int i = 0; i < 32; i++) {
            float2 va = pa[i], vb = pb[i];
            wA[i] = pk2(scA * va.x, scA * va.y);
            wB[i] = pk2(scB * vb.x, scB * vb.y);
        }
    }

    const float aB = odd ? 0.5f : 1.0f;
    const float oB = odd ? 0.5f : 0.0f;

    float c = odd ? c0[u] : 0.0f;
    float h = 0.0f;
    if (tid < H_DIM) h_sh[0][tid] = h0[tid];

#define STEP(XA, XB, RB, WB) do {                                             \
        __syncthreads();                                                      \
        const ulonglong2* hp = (const ulonglong2*)h_sh[RB];                   \
        ull a0 = 0, a1 = 0, a2 = 0, a3 = 0;                                   \
        ull b0 = 0, b1 = 0, b2 = 0, b3 = 0;                                   \
        _Pragma("unroll")                                                     \
        for (int i = 0; i < 8; i++) {                                         \
            ulonglong2 hv = hp[2 * i], hw = hp[2 * i + 1];                    \
            a0 = fma2(hv.x, wA[4 * i + 0], a0);                               \
            b0 = fma2(hv.x, wB[4 * i + 0], b0);                               \
            a1 = fma2(hv.y, wA[4 * i + 1], a1);                               \
            b1 = fma2(hv.y, wB[4 * i + 1], b1);                               \
            a2 = fma2(hw.x, wA[4 * i + 2], a2);                               \
            b2 = fma2(hw.x, wB[4 * i + 2], b2);                               \
            a3 = fma2(hw.y, wA[4 * i + 3], a3);                               \
            b3 = fma2(hw.y, wB[4 * i + 3], b3);                               \
        }                                                                     \
        float2 sA = upk(add2(add2(a0, a1), add2(a2, a3)));                    \
        float2 sB = upk(add2(add2(b0, b1), add2(b2, b3)));                    \
        float preA = (XA) + sA.x + sA.y;                                      \
        float preB = (XB) + sB.x + sB.y;                                      \
        float vA = fmaf(0.5f, tanhap(preA), 0.5f);   /* sigmoid (pre-scaled)*/\
        float vB = fmaf(aB, tanhap(preB), oB);       /* tanh / sigmoid */     \
        float pr = __shfl_sync(0xffffffffu, vA * vB, l & 30);  /* i*g~ */     \
        if (odd) {                                                            \
            c = fmaf(vA, c, pr);            /* c = f*c + i*g~ */              \
            h = vB * tanhap(c);             /* h = o*tanh(c) */               \
            h_sh[WB][u] = h;                                                  \
        }                                                                     \
    } while (0)

    // Streamed xg: one LDG.128 pair per 4 steps, prefetched 2 blocks ahead
    // (padded arrays -> no bounds predicate).
    float4 xA0 = g_xgA[tid],       xB0 = g_xgB[tid];
    float4 xA1 = g_xgA[128 + tid], xB1 = g_xgB[128 + tid];
    for (int tb = 0; tb < NT4; tb++) {
        float4 xA2 = g_xgA[(size_t)(tb + 2) * 128 + tid];
        float4 xB2 = g_xgB[(size_t)(tb + 2) * 128 + tid];
        STEP(xA0.x, xB0.x, 0, 1);
        STEP(xA0.y, xB0.y, 1, 0);
        STEP(xA0.z, xB0.z, 0, 1);
        STEP(xA0.w, xB0.w, 1, 0);
        xA0 = xA1; xA1 = xA2;
        xB0 = xB1; xB1 = xB2;
    }
#undef STEP

    if (odd) g_hfin[u] = h;
}

// =====================================================================
// Kernel 3: out[f] = sigmoid(h_last . W_fc[f] + b_fc[f]),  f < 512
// =====================================================================
__global__ void fc_out(const float* __restrict__ Wfc,
                       const float* __restrict__ bfc,
                       float* __restrict__ out) {
    __shared__ float hsm[H_DIM];
    const int tid = threadIdx.x;   // 0..511
    if (tid < H_DIM) hsm[tid] = g_hfin[tid];
    __syncthreads();
    float acc = bfc[tid];
    const float* wr = Wfc + (size_t)tid * H_DIM;
#pragma unroll
    for (int k = 0; k < H_DIM; k++) acc = fmaf(wr[k], hsm[k], acc);
    out[tid] = 1.0f / (1.0f + __expf(-acc));
}

extern "C" void kernel_launch(void* const* d_in, const int* in_sizes, int n_in,
                              void* d_out, int out_size) {
    const float* x   = (const float*)d_in[0];
    const float* h0  = (const float*)d_in[1];
    const float* c0  = (const float*)d_in[2];
    const float* Wih = (const float*)d_in[3];
    const float* Whh = (const float*)d_in[4];
    const float* bih = (const float*)d_in[5];
    const float* bhh = (const float*)d_in[6];
    const float* Wfc = (const float*)d_in[7];
    const float* bfc = (const float*)d_in[8];
    float* out = (float*)d_out;

    dim3 ggrid(G_DIM / BN, T_SEQ / BM);   // x = colgroup (2), y = t-tile (512)
    gemm_xg<<<ggrid, 512>>>(x, Wih, bih, bhh);
    lstm_rec<<<1, 128>>>(Whh, h0, c0);
    fc_out<<<1, 512>>>(Wfc, bfc, out);
}

// round 17
// speedup vs baseline: 1.0221x; 1.0032x over previous
#include <cuda_runtime.h>
#include <cuda_bf16.h>
#include <cstdint>

// Problem constants
#define T_SEQ 65536
#define F_IN  512
#define H_DIM 64
#define G_DIM 256    // 4*H
#define NT4   (T_SEQ / 4)

typedef unsigned long long ull;

// Scratch (allocation-free rule: __device__ globals)
__device__ __align__(16) float4 g_xgA[(size_t)(NT4 + 2) * 128];
__device__ __align__(16) float4 g_xgB[(size_t)(NT4 + 2) * 128];

// ---------------- packed f32x2 helpers ----------------
static __device__ __forceinline__ ull fma2(ull a, ull b, ull c) {
    ull d;
    asm("fma.rn.f32x2 %0, %1, %2, %3;" : "=l"(d) : "l"(a), "l"(b), "l"(c));
    return d;
}
static __device__ __forceinline__ ull add2(ull a, ull b) {
    ull d;
    asm("add.rn.f32x2 %0, %1, %2;" : "=l"(d) : "l"(a), "l"(b));
    return d;
}
static __device__ __forceinline__ float2 upk(ull a) {
    float2 r;
    asm("mov.b64 {%0, %1}, %2;" : "=f"(r.x), "=f"(r.y) : "l"(a));
    return r;
}
static __device__ __forceinline__ ull pk2(float x, float y) {
    ull r;
    asm("mov.b64 %0, {%1, %2};" : "=l"(r) : "f"(x), "f"(y));
    return r;
}

// ---------------- single-instruction MUFU.TANH ----------------
static __device__ __forceinline__ float tanhap(float x) {
    float r;
    asm("tanh.approx.f32 %0, %1;" : "=f"(r) : "f"(x));
    return r;
}

// Recurrence thread mapping for gate-row r (= g*64 + u):
// warp w = u>>4 owns units [16w,16w+16); even lane: gates (i,g); odd: (f,o)
static __device__ __forceinline__ int map_tid(int g, int u) {
    int odd = g & 1;                 // i,g -> even ; f,o -> odd
    return ((u >> 4) << 5) + ((u & 15) << 1) + odd;
}

// =====================================================================
// Kernel 1: xg = x @ W_ih.T + (b_ih + b_hh), permuted into slot streams.
// R14 config (measured best: 320us): BM=128, BN=128, 256 threads,
// double-buffered smem, f32x2 inner loop with row-pair packed
// accumulators. Thread tile 8 rows x 8 cols; cols split tx*4 / 64+tx*4.
// Per kk: 4x LDS.128 + 8 dup-MOV + 32 fma2 for 64 MACs.
// k-order per (row,col) identical -> xg bit-identical to prior rounds.
// Grid: blockIdx.x = colgroup (2), blockIdx.y = t-tile (512) for L2 x-reuse.
// =====================================================================
#define BM 128
#define BN 128
#define XSTRIDE 132   // 128 + 4 pad floats (16B-aligned rows)
#define NKT (F_IN / 16)
__global__ void __launch_bounds__(256)
gemm_xg(const float* __restrict__ x,
        const float* __restrict__ Wih,
        const float* __restrict__ bih,
        const float* __restrict__ bhh) {
    __shared__ __align__(16) float xsT[2][16][XSTRIDE];   // [buf][kk][row]
    __shared__ __align__(16) float wsT[2][16][XSTRIDE];   // [buf][kk][col]
    const int tid = threadIdx.x;           // 0..255
    const int tx = tid & 15;               // col group
    const int ty = tid >> 4;               // row group: rows ty*8..ty*8+7
    const int row0 = blockIdx.y * BM;      // t-tile base
    const int col0 = blockIdx.x * BN;      // gate-row tile base

    ull acc2[4][8];
#pragma unroll
    for (int i = 0; i < 4; i++)
#pragma unroll
        for (int j = 0; j < 8; j++) acc2[i][j] = 0ull;

    // Loader: both tiles are 128x16 = 512 float4 slots, 2 per thread.
    const int r0 = tid >> 2, r1 = (tid + 256) >> 2;
    const int kq = (tid & 3) * 4;

#define STS_TILE(BUF, XV0, XV1, WV0, WV1) do {                                \
        xsT[BUF][kq + 0][r0] = (XV0).x; xsT[BUF][kq + 1][r0] = (XV0).y;       \
        xsT[BUF][kq + 2][r0] = (XV0).z; xsT[BUF][kq + 3][r0] = (XV0).w;       \
        xsT[BUF][kq + 0][r1] = (XV1).x; xsT[BUF][kq + 1][r1] = (XV1).y;       \
        xsT[BUF][kq + 2][r1] = (XV1).z; xsT[BUF][kq + 3][r1] = (XV1).w;       \
        wsT[BUF][kq + 0][r0] = (WV0).x; wsT[BUF][kq + 1][r0] = (WV0).y;       \
        wsT[BUF][kq + 2][r0] = (WV0).z; wsT[BUF][kq + 3][r0] = (WV0).w;       \
        wsT[BUF][kq + 0][r1] = (WV1).x; wsT[BUF][kq + 1][r1] = (WV1).y;       \
        wsT[BUF][kq + 2][r1] = (WV1).z; wsT[BUF][kq + 3][r1] = (WV1).w;       \
    } while (0)

    // Prologue: load ktile 0 into buffer 0.
    {
        float4 xv0 = *(const float4*)(x + (size_t)(row0 + r0) * F_IN + kq);
        float4 xv1 = *(const float4*)(x + (size_t)(row0 + r1) * F_IN + kq);
        float4 wv0 = *(const float4*)(Wih + (size_t)(col0 + r0) * F_IN + kq);
        float4 wv1 = *(const float4*)(Wih + (size_t)(col0 + r1) * F_IN + kq);
        STS_TILE(0, xv0, xv1, wv0, wv1);
    }
    __syncthreads();

    for (int kt = 0; kt < NKT; kt++) {
        const int cur = kt & 1;
        float4 nx0, nx1, nw0, nw1;
        if (kt + 1 < NKT) {
            const int kb = (kt + 1) * 16 + kq;
            nx0 = *(const float4*)(x + (size_t)(row0 + r0) * F_IN + kb);
            nx1 = *(const float4*)(x + (size_t)(row0 + r1) * F_IN + kb);
            nw0 = *(const float4*)(Wih + (size_t)(col0 + r0) * F_IN + kb);
            nw1 = *(const float4*)(Wih + (size_t)(col0 + r1) * F_IN + kb);
        }
#pragma unroll
        for (int kk = 0; kk < 16; kk++) {
            ulonglong2 a01 = *(const ulonglong2*)&xsT[cur][kk][ty * 8];
            ulonglong2 a23 = *(const ulonglong2*)&xsT[cur][kk][ty * 8 + 4];
            float4 bv0 = *(const float4*)&wsT[cur][kk][tx * 4];
            float4 bv1 = *(const float4*)&wsT[cur][kk][64 + tx * 4];
            ull b0 = pk2(bv0.x, bv0.x), b1 = pk2(bv0.y, bv0.y);
            ull b2 = pk2(bv0.z, bv0.z), b3 = pk2(bv0.w, bv0.w);
            ull b4 = pk2(bv1.x, bv1.x), b5 = pk2(bv1.y, bv1.y);
            ull b6 = pk2(bv1.z, bv1.z), b7 = pk2(bv1.w, bv1.w);
            acc2[0][0] = fma2(a01.x, b0, acc2[0][0]);
            acc2[0][1] = fma2(a01.x, b1, acc2[0][1]);
            acc2[0][2] = fma2(a01.x, b2, acc2[0][2]);
            acc2[0][3] = fma2(a01.x, b3, acc2[0][3]);
            acc2[0][4] = fma2(a01.x, b4, acc2[0][4]);
            acc2[0][5] = fma2(a01.x, b5, acc2[0][5]);
            acc2[0][6] = fma2(a01.x, b6, acc2[0][6]);
            acc2[0][7] = fma2(a01.x, b7, acc2[0][7]);
            acc2[1][0] = fma2(a01.y, b0, acc2[1][0]);
            acc2[1][1] = fma2(a01.y, b1, acc2[1][1]);
            acc2[1][2] = fma2(a01.y, b2, acc2[1][2]);
            acc2[1][3] = fma2(a01.y, b3, acc2[1][3]);
            acc2[1][4] = fma2(a01.y, b4, acc2[1][4]);
            acc2[1][5] = fma2(a01.y, b5, acc2[1][5]);
            acc2[1][6] = fma2(a01.y, b6, acc2[1][6]);
            acc2[1][7] = fma2(a01.y, b7, acc2[1][7]);
            acc2[2][0] = fma2(a23.x, b0, acc2[2][0]);
            acc2[2][1] = fma2(a23.x, b1, acc2[2][1]);
            acc2[2][2] = fma2(a23.x, b2, acc2[2][2]);
            acc2[2][3] = fma2(a23.x, b3, acc2[2][3]);
            acc2[2][4] = fma2(a23.x, b4, acc2[2][4]);
            acc2[2][5] = fma2(a23.x, b5, acc2[2][5]);
            acc2[2][6] = fma2(a23.x, b6, acc2[2][6]);
            acc2[2][7] = fma2(a23.x, b7, acc2[2][7]);
            acc2[3][0] = fma2(a23.y, b0, acc2[3][0]);
            acc2[3][1] = fma2(a23.y, b1, acc2[3][1]);
            acc2[3][2] = fma2(a23.y, b2, acc2[3][2]);
            acc2[3][3] = fma2(a23.y, b3, acc2[3][3]);
            acc2[3][4] = fma2(a23.y, b4, acc2[3][4]);
            acc2[3][5] = fma2(a23.y, b5, acc2[3][5]);
            acc2[3][6] = fma2(a23.y, b6, acc2[3][6]);
            acc2[3][7] = fma2(a23.y, b7, acc2[3][7]);
        }
        if (kt + 1 < NKT) STS_TILE(cur ^ 1, nx0, nx1, nw0, nw1);
        __syncthreads();
    }
#undef STS_TILE

    // Epilogue: thread's 8 rows = 2 float4 t-blocks; 8 cols (two groups).
    const int tb4 = (row0 + ty * 8) >> 2;
#pragma unroll
    for (int jj = 0; jj < 8; jj++) {
        const int col = col0 + ((jj < 4) ? (tx * 4 + jj) : (64 + tx * 4 + jj - 4));
        const float bj = bih[col] + bhh[col];
        const int gg = col >> 6;            // gate 0=i 1=f 2=g 3=o
        const int uu = col & 63;
        const int p = map_tid(gg, uu);
        const float sc = (gg == 2) ? 1.0f : 0.5f;   // sigmoid pre-scale (exact)
        float v[8];
#pragma unroll
        for (int rp = 0; rp < 4; rp++) {
            float2 pv = upk(acc2[rp][jj]);
            v[2 * rp] = pv.x;
            v[2 * rp + 1] = pv.y;
        }
        float4* buf = (gg >= 2) ? g_xgB : g_xgA;    // slot B = gates g,o
#pragma unroll
        for (int m = 0; m < 2; m++) {
            float4 o;
            o.x = sc * (v[4 * m + 0] + bj);
            o.y = sc * (v[4 * m + 1] + bj);
            o.z = sc * (v[4 * m + 2] + bj);
            o.w = sc * (v[4 * m + 3] + bj);
            buf[(size_t)(tb4 + m) * 128 + p] = o;
        }
    }
}

// =====================================================================
// Kernel 2: persistent single-block LSTM recurrence, 128 threads
// (4 warps, 1 per SMSP), with the final FC + sigmoid FUSED at the tail
// (final h lives in h_sh[0]; 128 threads compute 4 outputs each in the
// exact scalar k-order of the old fc_out kernel -> identical results,
// one fewer launch and no g_hfin DRAM round-trip).
// =====================================================================
__global__ void __launch_bounds__(128, 1)
lstm_rec(const float* __restrict__ Whh,
         const float* __restrict__ h0,
         const float* __restrict__ c0,
         const float* __restrict__ Wfc,
         const float* __restrict__ bfc,
         float* __restrict__ out) {
    __shared__ __align__(16) float h_sh[2][H_DIM];
    const int tid = threadIdx.x;          // 0..127
    const int l = tid & 31;
    const int u = ((tid >> 5) << 4) + (l >> 1);   // hidden unit
    const int odd = l & 1;
    const int rA = (odd ? 64 : 0) + u;    // i or f   (sigmoid: pre-scale 0.5)
    const int rB = (odd ? 192 : 128) + u; // g or o   (tanh 1.0 / sigmoid 0.5)
    const float scA = 0.5f;
    const float scB = odd ? 0.5f : 1.0f;

    // W_hh rows -> packed f32x2 registers, pre-scaled (x0.5 exact)
    ull wA[32], wB[32];
    {
        const float2* pa = (const float2*)(Whh + (size_t)rA * H_DIM);
        const float2* pb = (const float2*)(Whh + (size_t)rB * H_DIM);
#pragma unroll
        for (int i = 0; i < 32; i++) {
            float2 va = pa[i], vb = pb[i];
            wA[i] = pk2(scA * va.x, scA * va.y);
            wB[i] = pk2(scB * vb.x, scB * vb.y);
        }
    }

    const float aB = odd ? 0.5f : 1.0f;
    const float oB = odd ? 0.5f : 0.0f;

    float c = odd ? c0[u] : 0.0f;
    float h = 0.0f;
    if (tid < H_DIM) h_sh[0][tid] = h0[tid];

#define STEP(XA, XB, RB, WB) do {                                             \
        __syncthreads();                                                      \
        const ulonglong2* hp = (const ulonglong2*)h_sh[RB];                   \
        ull a0 = 0, a1 = 0, a2 = 0, a3 = 0;                                   \
        ull b0 = 0, b1 = 0, b2 = 0, b3 = 0;                                   \
        _Pragma("unroll")                                                     \
        for (int i = 0; i < 8; i++) {                                         \
            ulonglong2 hv = hp[2 * i], hw = hp[2 * i + 1];                    \
            a0 = fma2(hv.x, wA[4 * i + 0], a0);                               \
            b0 = fma2(hv.x, wB[4 * i + 0], b0);                               \
            a1 = fma2(hv.y, wA[4 * i + 1], a1);                               \
            b1 = fma2(hv.y, wB[4 * i + 1], b1);                               \
            a2 = fma2(hw.x, wA[4 * i + 2], a2);                               \
            b2 = fma2(hw.x, wB[4 * i + 2], b2);                               \
            a3 = fma2(hw.y, wA[4 * i + 3], a3);                               \
            b3 = fma2(hw.y, wB[4 * i + 3], b3);                               \
        }                                                                     \
        float2 sA = upk(add2(add2(a0, a1), add2(a2, a3)));                    \
        float2 sB = upk(add2(add2(b0, b1), add2(b2, b3)));                    \
        float preA = (XA) + sA.x + sA.y;                                      \
        float preB = (XB) + sB.x + sB.y;                                      \
        float vA = fmaf(0.5f, tanhap(preA), 0.5f);   /* sigmoid (pre-scaled)*/\
        float vB = fmaf(aB, tanhap(preB), oB);       /* tanh / sigmoid */     \
        float pr = __shfl_sync(0xffffffffu, vA * vB, l & 30);  /* i*g~ */     \
        if (odd) {                                                            \
            c = fmaf(vA, c, pr);            /* c = f*c + i*g~ */              \
            h = vB * tanhap(c);             /* h = o*tanh(c) */               \
            h_sh[WB][u] = h;                                                  \
        }                                                                     \
    } while (0)

    // Streamed xg: one LDG.128 pair per 4 steps, prefetched 2 blocks ahead
    // (padded arrays -> no bounds predicate).
    float4 xA0 = g_xgA[tid],       xB0 = g_xgB[tid];
    float4 xA1 = g_xgA[128 + tid], xB1 = g_xgB[128 + tid];
    for (int tb = 0; tb < NT4; tb++) {
        float4 xA2 = g_xgA[(size_t)(tb + 2) * 128 + tid];
        float4 xB2 = g_xgB[(size_t)(tb + 2) * 128 + tid];
        STEP(xA0.x, xB0.x, 0, 1);
        STEP(xA0.y, xB0.y, 1, 0);
        STEP(xA0.z, xB0.z, 0, 1);
        STEP(xA0.w, xB0.w, 1, 0);
        xA0 = xA1; xA1 = xA2;
        xB0 = xB1; xB1 = xB2;
    }
#undef STEP

    // ----- fused FC + sigmoid tail -----
    // Final h is in h_sh[0] (last STEP wrote buffer 0); also store from
    // register for robustness, then one barrier before the block-wide read.
    if (odd) h_sh[0][u] = h;
    __syncthreads();
#pragma unroll
    for (int j = 0; j < 4; j++) {
        const int f = tid * 4 + j;          // 0..511
        float acc = bfc[f];
        const float* wr = Wfc + (size_t)f * H_DIM;
#pragma unroll
        for (int k = 0; k < H_DIM; k++) acc = fmaf(wr[k], h_sh[0][k], acc);
        out[f] = 1.0f / (1.0f + __expf(-acc));
    }
}

extern "C" void kernel_launch(void* const* d_in, const int* in_sizes, int n_in,
                              void* d_out, int out_size) {
    const float* x   = (const float*)d_in[0];
    const float* h0  = (const float*)d_in[1];
    const float* c0  = (const float*)d_in[2];
    const float* Wih = (const float*)d_in[3];
    const float* Whh = (const float*)d_in[4];
    const float* bih = (const float*)d_in[5];
    const float* bhh = (const float*)d_in[6];
    const float* Wfc = (const float*)d_in[7];
    const float* bfc = (const float*)d_in[8];
    float* out = (float*)d_out;

    dim3 ggrid(G_DIM / BN, T_SEQ / BM);   // x = colgroup (2), y = t-tile (512)
    gemm_xg<<<ggrid, 256>>>(x, Wih, bih, bhh);
    lstm_rec<<<1, 128>>>(Whh, h0, c0, Wfc, bfc, out);
}